// round 1
// baseline (speedup 1.0000x reference)
#include <cuda_runtime.h>

// NeuralODE RK4: B=2048 rows split across 128 persistent CTAs (16 rows each).
// Rows are independent -> no inter-CTA sync ever. Each CTA runs the whole
// 99-step RK4 chain on its row block using packed fp32x2 FMA.
//
// State layout in SMEM: row-pair packed float2  v2[p][col] = (x[2p][col], x[2p+1][col])
// so LDS.64 yields a ready-packed f32x2 A-operand for fma.rn.f32x2.

#define B_DIM   2048
#define F_DIM   256
#define H_DIM   1024
#define NSTEPS  100
#define ROWS    16
#define RP      8            // row pairs per CTA
#define NTHREADS 256
#define NCTA    (B_DIM / ROWS)   // 128

typedef unsigned long long ull;

__device__ __forceinline__ void fma2(ull &d, ull a, ull b) {
    asm("fma.rn.f32x2 %0, %1, %2, %0;" : "+l"(d) : "l"(a), "l"(b));
}
__device__ __forceinline__ ull pack2(float x, float y) {
    ull r; asm("mov.b64 %0, {%1, %2};" : "=l"(r) : "f"(x), "f"(y)); return r;
}
__device__ __forceinline__ float2 unpack2(ull v) {
    float2 f; asm("mov.b64 {%0, %1}, %2;" : "=f"(f.x), "=f"(f.y) : "l"(v)); return f;
}

__global__ __launch_bounds__(NTHREADS, 1)
void node_rk4_kernel(const float* __restrict__ x,
                     const float* __restrict__ W1,
                     const float* __restrict__ b1,
                     const float* __restrict__ W2,
                     const float* __restrict__ b2,
                     float* __restrict__ out)
{
    extern __shared__ ull sm[];
    ull* xe2 = sm;                    // RP * F_DIM   (eval state)
    ull* xc2 = xe2 + RP * F_DIM;      // RP * F_DIM   (base state at step start)
    ull* hs2 = xc2 + RP * F_DIM;      // RP * H_DIM   (hidden activations)

    const int tid = threadIdx.x;
    const int r0  = blockIdx.x * ROWS;

    // ---- init: load x block, emit out[0], fill xc2/xe2 ----
    for (int i = tid; i < ROWS * F_DIM; i += NTHREADS) {
        int row = i >> 8;          // / F_DIM
        int col = i & (F_DIM - 1);
        float v = x[(size_t)(r0 + row) * F_DIM + col];
        out[(size_t)(r0 + row) * F_DIM + col] = v;     // slab 0 = x
        float* dst = (float*)&xc2[(row >> 1) * F_DIM + col];
        dst[row & 1] = v;
    }
    __syncthreads();
    for (int i = tid; i < RP * F_DIM; i += NTHREADS) xe2[i] = xc2[i];

    // ---- per-thread constants ----
    const float* wtp = W1 + (size_t)F_DIM * H_DIM;     // time row of W1
    float wt_j[4], b1_j[4];
    #pragma unroll
    for (int j = 0; j < 4; ++j) {
        wt_j[j] = wtp[tid + 256 * j];
        b1_j[j] = b1[tid + 256 * j];
    }
    const int c2 = tid & 127;       // column-pair index for GEMM2
    const int rh = tid >> 7;        // row-half for GEMM2
    float b2c0 = b2[2 * c2];
    float b2c1 = b2[2 * c2 + 1];

    const float dt  = 1.0f / 99.0f;
    const float dt6 = dt * (1.0f / 6.0f);

    float2 acc_rk[4][2];            // k1 + 2k2 + 2k3 + k4 accumulator (thread-owned tile)

    __syncthreads();

    for (int s = 0; s < NSTEPS - 1; ++s) {
        float t0 = (float)s * dt;
        #pragma unroll 1
        for (int e = 0; e < 4; ++e) {
            float te = t0 + ((e == 0) ? 0.0f : (e == 3) ? dt : 0.5f * dt);

            // ============ GEMM1: h = tanh(xe @ Wx + te*wt + b1) ============
            // thread tile: all 8 row-pairs x 4 columns {tid, tid+256, tid+512, tid+768}
            ull acc1[RP][4];
            #pragma unroll
            for (int p = 0; p < RP; ++p)
                #pragma unroll
                for (int j = 0; j < 4; ++j) acc1[p][j] = 0ull;

            const float* wbase = W1 + tid;
            #pragma unroll 4
            for (int k = 0; k < F_DIM; ++k) {
                ull xk[RP];
                #pragma unroll
                for (int p = 0; p < RP; ++p) xk[p] = xe2[p * F_DIM + k];
                ull w2v[4];
                #pragma unroll
                for (int j = 0; j < 4; ++j) {
                    float w = __ldg(wbase + (size_t)k * H_DIM + 256 * j);
                    w2v[j] = pack2(w, w);
                }
                #pragma unroll
                for (int p = 0; p < RP; ++p) {
                    #pragma unroll
                    for (int j = 0; j < 4; ++j) fma2(acc1[p][j], xk[p], w2v[j]);
                }
            }
            // epilogue: bias + tanh, write hidden to SMEM
            #pragma unroll
            for (int p = 0; p < RP; ++p) {
                #pragma unroll
                for (int j = 0; j < 4; ++j) {
                    float2 v = unpack2(acc1[p][j]);
                    float bias = te * wt_j[j] + b1_j[j];
                    v.x = tanhf(v.x + bias);
                    v.y = tanhf(v.y + bias);
                    hs2[p * H_DIM + tid + 256 * j] = pack2(v.x, v.y);
                }
            }
            __syncthreads();   // hs2 visible to all before GEMM2 reads

            // ============ GEMM2: k = h @ W2 + b2 ============
            // thread tile: row-pairs {rh*4 .. rh*4+3} x cols {2*c2, 2*c2+1}
            ull acc2[4][2];
            #pragma unroll
            for (int i = 0; i < 4; ++i) { acc2[i][0] = 0ull; acc2[i][1] = 0ull; }

            const float2* w2base = ((const float2*)W2) + c2;
            const int pbase = rh * 4;
            #pragma unroll 4
            for (int k = 0; k < H_DIM; ++k) {
                ull hk[4];
                #pragma unroll
                for (int i = 0; i < 4; ++i) hk[i] = hs2[(pbase + i) * H_DIM + k];
                float2 w = __ldg(&w2base[(size_t)k * 128]);
                ull w0 = pack2(w.x, w.x);
                ull w1 = pack2(w.y, w.y);
                #pragma unroll
                for (int i = 0; i < 4; ++i) {
                    fma2(acc2[i][0], hk[i], w0);
                    fma2(acc2[i][1], hk[i], w1);
                }
            }

            // epilogue: RK4 state machine (thread-owned slots only; no race)
            float ae = (e == 3) ? 0.0f : ((e == 2) ? dt : 0.5f * dt);
            float be = (e == 1 || e == 2) ? 2.0f : 1.0f;
            #pragma unroll
            for (int i = 0; i < 4; ++i) {
                int p = pbase + i;
                #pragma unroll
                for (int c = 0; c < 2; ++c) {
                    float2 kv = unpack2(acc2[i][c]);
                    float bb = (c == 0) ? b2c0 : b2c1;
                    kv.x += bb; kv.y += bb;
                    if (e == 0) {
                        acc_rk[i][c].x = kv.x;
                        acc_rk[i][c].y = kv.y;
                    } else {
                        acc_rk[i][c].x += be * kv.x;
                        acc_rk[i][c].y += be * kv.y;
                    }
                    int col = 2 * c2 + c;
                    float2 xc = unpack2(xc2[p * F_DIM + col]);
                    float2 xe;
                    if (e < 3) {
                        xe.x = xc.x + ae * kv.x;
                        xe.y = xc.y + ae * kv.y;
                    } else {
                        xe.x = xc.x + dt6 * acc_rk[i][c].x;
                        xe.y = xc.y + dt6 * acc_rk[i][c].y;
                        xc2[p * F_DIM + col] = pack2(xe.x, xe.y);
                        size_t ob = (size_t)(s + 1) * B_DIM * F_DIM;
                        out[ob + (size_t)(r0 + 2 * p)     * F_DIM + col] = xe.x;
                        out[ob + (size_t)(r0 + 2 * p + 1) * F_DIM + col] = xe.y;
                    }
                    xe2[p * F_DIM + col] = pack2(xe.x, xe.y);
                }
            }
            __syncthreads();   // xe2 update visible before next GEMM1
        }
    }
}

extern "C" void kernel_launch(void* const* d_in, const int* in_sizes, int n_in,
                              void* d_out, int out_size) {
    (void)in_sizes; (void)n_in; (void)out_size;
    const float* x  = (const float*)d_in[0];
    const float* W1 = (const float*)d_in[1];
    const float* b1 = (const float*)d_in[2];
    const float* W2 = (const float*)d_in[3];
    const float* b2 = (const float*)d_in[4];
    float* out = (float*)d_out;

    const size_t smem = (size_t)(2 * RP * F_DIM + RP * H_DIM) * sizeof(ull); // 96 KB
    cudaFuncSetAttribute(node_rk4_kernel,
                         cudaFuncAttributeMaxDynamicSharedMemorySize, (int)smem);
    node_rk4_kernel<<<NCTA, NTHREADS, smem>>>(x, W1, b1, W2, b2, out);
}

// round 2
// speedup vs baseline: 1.2647x; 1.2647x over previous
#include <cuda_runtime.h>

// NeuralODE RK4, round 2: 256 persistent CTAs x 8 rows, 2 CTAs/SM (16 warps/SM).
// Row-pair packed fp32x2 FMA; GEMM1 weights via LDG.128 with permuted hidden
// layout so STS stays conflict-free and GEMM2 walks W2 rows in permuted order.

#define B_DIM   2048
#define F_DIM   256
#define H_DIM   1024
#define NSTEPS  100
#define ROWS    8
#define RP      4            // row pairs per CTA
#define NTHREADS 256
#define NCTA    (B_DIM / ROWS)   // 256

typedef unsigned long long ull;

__device__ __forceinline__ void fma2(ull &d, ull a, ull b) {
    asm("fma.rn.f32x2 %0, %1, %2, %0;" : "+l"(d) : "l"(a), "l"(b));
}
__device__ __forceinline__ ull pack2(float x, float y) {
    ull r; asm("mov.b64 %0, {%1, %2};" : "=l"(r) : "f"(x), "f"(y)); return r;
}
__device__ __forceinline__ float2 unpack2(ull v) {
    float2 f; asm("mov.b64 {%0, %1}, %2;" : "=f"(f.x), "=f"(f.y) : "l"(v)); return f;
}

__global__ __launch_bounds__(NTHREADS, 2)
void node_rk4_kernel(const float* __restrict__ x,
                     const float* __restrict__ W1,
                     const float* __restrict__ b1,
                     const float* __restrict__ W2,
                     const float* __restrict__ b2,
                     float* __restrict__ out)
{
    extern __shared__ ull sm[];
    ull* xe2 = sm;                    // RP * F_DIM   (eval state)
    ull* xc2 = xe2 + RP * F_DIM;      // RP * F_DIM   (base state at step start)
    ull* hs2 = xc2 + RP * F_DIM;      // RP * H_DIM   (hidden, permuted: m = c*256 + t, col j = 4t+c)

    const int tid = threadIdx.x;
    const int r0  = blockIdx.x * ROWS;

    // ---- init: load x block, emit out[0], fill xc2/xe2 ----
    for (int i = tid; i < ROWS * F_DIM; i += NTHREADS) {
        int row = i >> 8;          // / F_DIM
        int col = i & (F_DIM - 1);
        float v = x[(size_t)(r0 + row) * F_DIM + col];
        out[(size_t)(r0 + row) * F_DIM + col] = v;     // slab 0 = x
        float* dst = (float*)&xc2[(row >> 1) * F_DIM + col];
        dst[row & 1] = v;
    }
    __syncthreads();
    for (int i = tid; i < RP * F_DIM; i += NTHREADS) xe2[i] = xc2[i];

    // ---- per-thread constants ----
    // GEMM1 columns owned by this thread: j = 4*tid + c, c in 0..3
    const float* wtp = W1 + (size_t)F_DIM * H_DIM;     // time row of W1
    const float4 wt4 = *((const float4*)wtp + tid);
    const float4 b14 = *((const float4*)b1 + tid);
    float wt_c[4] = {wt4.x, wt4.y, wt4.z, wt4.w};
    float b1_c[4] = {b14.x, b14.y, b14.z, b14.w};

    // GEMM2 tile: pairs {pb, pb+1}, column pair c2
    const int c2 = tid & 127;
    const int pb = (tid >> 7) * 2;
    const float2 b2v = *((const float2*)b2 + c2);

    const float dt  = 1.0f / 99.0f;
    const float dt6 = dt * (1.0f / 6.0f);

    float2 acc_rk[2][2];            // RK4 combined-k accumulator (thread-owned tile)

    __syncthreads();

    for (int s = 0; s < NSTEPS - 1; ++s) {
        float t0 = (float)s * dt;
        #pragma unroll 1
        for (int e = 0; e < 4; ++e) {
            float te = t0 + ((e == 0) ? 0.0f : (e == 3) ? dt : 0.5f * dt);

            // ============ GEMM1: h = tanh(xe @ Wx + te*wt + b1) ============
            ull acc1[RP][4];
            #pragma unroll
            for (int p = 0; p < RP; ++p)
                #pragma unroll
                for (int c = 0; c < 4; ++c) acc1[p][c] = 0ull;

            const float4* wptr = (const float4*)W1 + tid;   // row stride = 256 float4
            #pragma unroll 4
            for (int k = 0; k < F_DIM; ++k) {
                ull xk[RP];
                #pragma unroll
                for (int p = 0; p < RP; ++p) xk[p] = xe2[p * F_DIM + k];
                float4 w = __ldg(wptr); wptr += H_DIM / 4;
                ull w0 = pack2(w.x, w.x);
                ull w1 = pack2(w.y, w.y);
                ull w2 = pack2(w.z, w.z);
                ull w3 = pack2(w.w, w.w);
                #pragma unroll
                for (int p = 0; p < RP; ++p) {
                    fma2(acc1[p][0], xk[p], w0);
                    fma2(acc1[p][1], xk[p], w1);
                    fma2(acc1[p][2], xk[p], w2);
                    fma2(acc1[p][3], xk[p], w3);
                }
            }
            // epilogue: bias + tanh; store permuted (m = c*256 + tid) -> conflict-free STS.64
            #pragma unroll
            for (int p = 0; p < RP; ++p) {
                #pragma unroll
                for (int c = 0; c < 4; ++c) {
                    float2 v = unpack2(acc1[p][c]);
                    float bias = te * wt_c[c] + b1_c[c];
                    v.x = tanhf(v.x + bias);
                    v.y = tanhf(v.y + bias);
                    hs2[p * H_DIM + (c << 8) + tid] = pack2(v.x, v.y);
                }
            }
            __syncthreads();   // hs2 visible to all before GEMM2 reads

            // ============ GEMM2: k = h @ W2 + b2 ============
            // Walk hidden storage m = hi*256 + t  <=>  logical row j = 4t + hi of W2.
            ull acc2[2][2];
            acc2[0][0] = 0ull; acc2[0][1] = 0ull;
            acc2[1][0] = 0ull; acc2[1][1] = 0ull;

            const float2* wp2 = (const float2*)W2 + c2;
            #pragma unroll 1
            for (int hi = 0; hi < 4; ++hi) {
                const ull* h0 = hs2 + pb * H_DIM + (hi << 8);
                const ull* h1 = h0 + H_DIM;
                const float2* wr = wp2 + (size_t)hi * (F_DIM / 2);   // row hi, step 4 rows
                #pragma unroll 4
                for (int t = 0; t < 256; ++t) {
                    ull a0 = h0[t];
                    ull a1 = h1[t];
                    float2 w = __ldg(wr); wr += 4 * (F_DIM / 2);
                    ull w0 = pack2(w.x, w.x);
                    ull w1 = pack2(w.y, w.y);
                    fma2(acc2[0][0], a0, w0);
                    fma2(acc2[0][1], a0, w1);
                    fma2(acc2[1][0], a1, w0);
                    fma2(acc2[1][1], a1, w1);
                }
            }

            // epilogue: RK4 state machine (thread-owned slots only)
            float ae = (e == 3) ? 0.0f : ((e == 2) ? dt : 0.5f * dt);
            float be = (e == 1 || e == 2) ? 2.0f : 1.0f;
            #pragma unroll
            for (int i = 0; i < 2; ++i) {
                int p = pb + i;
                #pragma unroll
                for (int c = 0; c < 2; ++c) {
                    float2 kv = unpack2(acc2[i][c]);
                    float bb = (c == 0) ? b2v.x : b2v.y;
                    kv.x += bb; kv.y += bb;
                    if (e == 0) {
                        acc_rk[i][c].x = kv.x;
                        acc_rk[i][c].y = kv.y;
                    } else {
                        acc_rk[i][c].x += be * kv.x;
                        acc_rk[i][c].y += be * kv.y;
                    }
                    int col = 2 * c2 + c;
                    float2 xc = unpack2(xc2[p * F_DIM + col]);
                    float2 xe;
                    if (e < 3) {
                        xe.x = xc.x + ae * kv.x;
                        xe.y = xc.y + ae * kv.y;
                    } else {
                        xe.x = xc.x + dt6 * acc_rk[i][c].x;
                        xe.y = xc.y + dt6 * acc_rk[i][c].y;
                        xc2[p * F_DIM + col] = pack2(xe.x, xe.y);
                        size_t ob = (size_t)(s + 1) * B_DIM * F_DIM;
                        out[ob + (size_t)(r0 + 2 * p)     * F_DIM + col] = xe.x;
                        out[ob + (size_t)(r0 + 2 * p + 1) * F_DIM + col] = xe.y;
                    }
                    xe2[p * F_DIM + col] = pack2(xe.x, xe.y);
                }
            }
            __syncthreads();   // xe2/hs2 reuse safe for next eval
        }
    }
}

extern "C" void kernel_launch(void* const* d_in, const int* in_sizes, int n_in,
                              void* d_out, int out_size) {
    (void)in_sizes; (void)n_in; (void)out_size;
    const float* x  = (const float*)d_in[0];
    const float* W1 = (const float*)d_in[1];
    const float* b1 = (const float*)d_in[2];
    const float* W2 = (const float*)d_in[3];
    const float* b2 = (const float*)d_in[4];
    float* out = (float*)d_out;

    const size_t smem = (size_t)(2 * RP * F_DIM + RP * H_DIM) * sizeof(ull); // 48 KB
    cudaFuncSetAttribute(node_rk4_kernel,
                         cudaFuncAttributeMaxDynamicSharedMemorySize, (int)smem);
    node_rk4_kernel<<<NCTA, NTHREADS, smem>>>(x, W1, b1, W2, b2, out);
}